// round 5
// baseline (speedup 1.0000x reference)
#include <cuda_runtime.h>
#include <cuda_fp16.h>
#include <cstdint>
#include <cstddef>

// ---------------------------------------------------------------------------
// Problem constants
// ---------------------------------------------------------------------------
#define BROWS  32768
#define DMODEL 1024
#define NHEADS 16
#define HDIM   64

static const int GN = DMODEL;

// Scratch (__device__ globals = allocation-guard-safe)
#define SLOT_ELEMS 33554432ull                 // B*D
__device__ float g_pool[11ull * SLOT_ELEMS];   // 7 fp32 slots + fp16 packed region
#define DD 1048576ull                          // D*D
__device__ float g_wr[5ull * DD + 16];         // 10*DD halves packed weights

// ---------------------------------------------------------------------------
// Helpers
// ---------------------------------------------------------------------------
__device__ __forceinline__ float gelu_exact(float x) {
    return 0.5f * x * (1.0f + erff(x * 0.70710678118654752440f));
}

// Packed-A (fp16) index: row-major activation [row, col] -> fragment-major.
// chunk(4096 halves = 8KB) = (mtile of 128 rows, kb of 32 cols).
// unit u = wm*256 + ks*128 + mt*32 + lane ; 8 halves per unit (4 regs x 2).
__device__ __forceinline__ size_t packA_idx_h(uint32_t row, uint32_t col) {
    uint32_t mtile = row >> 7, r = row & 127;
    uint32_t wm = r >> 6, mt = (r >> 4) & 3, b8 = (r >> 3) & 1, g = r & 7;
    uint32_t kb = col >> 5, c5 = col & 31;
    uint32_t ks = c5 >> 4, c4 = c5 & 15;
    uint32_t hi8 = c4 >> 3, rem = c4 & 7, tig = rem >> 1, lo = rem & 1;
    uint32_t reg = hi8 * 2 + b8;
    uint32_t u = ((wm * 2 + ks) * 4 + mt) * 32 + g * 4 + tig;
    return (((size_t)(mtile * 32 + kb)) << 12) + u * 8 + reg * 2 + lo;
}

// ---------------------------------------------------------------------------
// Pack kernels: fp32 -> fp16 (RN) + fragment-major reorder
// ---------------------------------------------------------------------------
__global__ void pack_a(const float* __restrict__ src, __half* __restrict__ dst, size_t n) {
    size_t i  = (size_t)blockIdx.x * blockDim.x + threadIdx.x;
    size_t st = (size_t)gridDim.x * blockDim.x;
    for (; i < n; i += st) {
        uint32_t chunk = (uint32_t)(i >> 12), w = (uint32_t)(i & 4095);
        uint32_t u = w >> 3, h = w & 7;
        uint32_t lane = u & 31, mt = (u >> 5) & 3, ks = (u >> 7) & 1, wm = (u >> 8) & 1;
        uint32_t mtile = chunk >> 5, kb = chunk & 31;
        uint32_t g = lane >> 2, tig = lane & 3;
        uint32_t reg = h >> 1, lo = h & 1;
        uint32_t row = mtile * 128 + wm * 64 + mt * 16 + (reg & 1) * 8 + g;
        uint32_t col = kb * 32 + ks * 16 + (reg >> 1) * 8 + tig * 2 + lo;
        dst[i] = __float2half_rn(src[(size_t)row * 1024 + col]);
    }
}
// Packed-W: chunk(8192 halves = 16KB) = (ntile of 256 N-rows, kb of 32 cols).
// unit u = wn*256 + ks*128 + p*32 + lane ; 16B unit = {b0,b1 of nt=2p, b0,b1 of nt=2p+1}
__global__ void pack_w(const float* __restrict__ src, __half* __restrict__ dst, size_t n) {
    size_t i  = (size_t)blockIdx.x * blockDim.x + threadIdx.x;
    size_t st = (size_t)gridDim.x * blockDim.x;
    for (; i < n; i += st) {
        uint32_t chunk = (uint32_t)(i >> 13), w = (uint32_t)(i & 8191);
        uint32_t u = w >> 3, h = w & 7;
        uint32_t lane = u & 31, p = (u >> 5) & 3, ks = (u >> 7) & 1, wn = (u >> 8) & 3;
        uint32_t ntile = chunk >> 5, kb = chunk & 31;
        uint32_t g = lane >> 2, tig = lane & 3;
        uint32_t reg = h >> 1;
        uint32_t nn = ntile * 256 + wn * 64 + p * 16 + (reg >> 1) * 8 + g;
        uint32_t kk = kb * 32 + ks * 16 + (reg & 1) * 8 + tig * 2 + (h & 1);
        dst[i] = __float2half_rn(src[(size_t)nn * 1024 + kk]);
    }
}

// ---------------------------------------------------------------------------
// fp16 GEMM (fp32 accum): C = A @ W^T + bias (optional GELU).
// CTA tile 128x256x32, 8 warps 2(M)x4(N), warp tile 64x64, mma.m16n8k16.
// Stage = 8KB A (512 uint4) + 16KB B (1024 uint4); 5 stages = 120KB smem.
// ---------------------------------------------------------------------------
#define NST 5
#define SMEM_GEMM (NST * 1536 * 16)   // 122880

template <bool GELU>
__global__ __launch_bounds__(256) void gemm_fp16(
    const uint4* __restrict__ Ap, const uint4* __restrict__ Wp,
    const float* __restrict__ bias, float* __restrict__ C)
{
    extern __shared__ uint4 sm4[];
    uint4* As = sm4;                 // NST * 512
    uint4* Bs = sm4 + NST * 512;     // NST * 1024

    const int tid  = threadIdx.x;
    const int ntb  = blockIdx.x;     // 0..3 (N tile of 256)
    const int mtb  = blockIdx.y;     // M tile of 128
    const int wid  = tid >> 5;
    const int lane = tid & 31;
    const int wm   = wid >> 2;       // 0..1
    const int wn   = wid & 3;        // 0..3
    const int g    = lane >> 2;
    const int tig  = lane & 3;

    const uint4* Abase = Ap + ((size_t)mtb * 32) * 512;
    const uint4* Bbase = Wp + ((size_t)ntb * 32) * 1024;

    auto load_stage = [&](int s, int c) {
        const uint4* ga = Abase + (size_t)c * 512 + tid;
        const uint4* gb = Bbase + (size_t)c * 1024 + tid;
        uint4* sa = As + s * 512 + tid;
        uint4* sb = Bs + s * 1024 + tid;
#pragma unroll
        for (int j = 0; j < 2; ++j) {
            uint32_t da = (uint32_t)__cvta_generic_to_shared(sa + j * 256);
            asm volatile("cp.async.cg.shared.global [%0], [%1], 16;\n" :: "r"(da), "l"(ga + j * 256));
        }
#pragma unroll
        for (int j = 0; j < 4; ++j) {
            uint32_t db = (uint32_t)__cvta_generic_to_shared(sb + j * 256);
            asm volatile("cp.async.cg.shared.global [%0], [%1], 16;\n" :: "r"(db), "l"(gb + j * 256));
        }
        asm volatile("cp.async.commit_group;\n");
    };

    float acc[4][8][4];
#pragma unroll
    for (int i = 0; i < 4; ++i)
#pragma unroll
        for (int j = 0; j < 8; ++j)
#pragma unroll
            for (int k = 0; k < 4; ++k) acc[i][j][k] = 0.f;

#pragma unroll
    for (int s = 0; s < NST - 1; ++s) load_stage(s, s);

    for (int c = 0; c < 32; ++c) {
        asm volatile("cp.async.wait_group %0;\n" :: "n"(NST - 2));
        __syncthreads();
        if (c + NST - 1 < 32) load_stage((c + NST - 1) % NST, c + NST - 1);

        const uint4* A4 = As + (c % NST) * 512  + wm * 256 + lane;
        const uint4* B4 = Bs + (c % NST) * 1024 + wn * 256 + lane;
#pragma unroll
        for (int ks = 0; ks < 2; ++ks) {
            uint4 av[4], bv[4];
#pragma unroll
            for (int mt = 0; mt < 4; ++mt) av[mt] = A4[ks * 128 + mt * 32];
#pragma unroll
            for (int p = 0; p < 4; ++p)  bv[p] = B4[ks * 128 + p * 32];
#pragma unroll
            for (int mt = 0; mt < 4; ++mt) {
#pragma unroll
                for (int p = 0; p < 4; ++p) {
                    asm volatile(
                        "mma.sync.aligned.m16n8k16.row.col.f32.f16.f16.f32 "
                        "{%0,%1,%2,%3}, {%4,%5,%6,%7}, {%8,%9}, {%0,%1,%2,%3};\n"
                        : "+f"(acc[mt][2*p][0]), "+f"(acc[mt][2*p][1]),
                          "+f"(acc[mt][2*p][2]), "+f"(acc[mt][2*p][3])
                        : "r"(av[mt].x), "r"(av[mt].y), "r"(av[mt].z), "r"(av[mt].w),
                          "r"(bv[p].x), "r"(bv[p].y));
                    asm volatile(
                        "mma.sync.aligned.m16n8k16.row.col.f32.f16.f16.f32 "
                        "{%0,%1,%2,%3}, {%4,%5,%6,%7}, {%8,%9}, {%0,%1,%2,%3};\n"
                        : "+f"(acc[mt][2*p+1][0]), "+f"(acc[mt][2*p+1][1]),
                          "+f"(acc[mt][2*p+1][2]), "+f"(acc[mt][2*p+1][3])
                        : "r"(av[mt].x), "r"(av[mt].y), "r"(av[mt].z), "r"(av[mt].w),
                          "r"(bv[p].z), "r"(bv[p].w));
                }
            }
        }
    }

    // epilogue
#pragma unroll
    for (int mt = 0; mt < 4; ++mt) {
#pragma unroll
        for (int nt = 0; nt < 8; ++nt) {
            int m = mtb * 128 + wm * 64 + mt * 16 + g;
            int n = ntb * 256 + wn * 64 + nt * 8 + tig * 2;
            float bv0 = bias ? bias[n]     : 0.f;
            float bv1 = bias ? bias[n + 1] : 0.f;
            float v0 = acc[mt][nt][0] + bv0;
            float v1 = acc[mt][nt][1] + bv1;
            float v2 = acc[mt][nt][2] + bv0;
            float v3 = acc[mt][nt][3] + bv1;
            if (GELU) {
                v0 = gelu_exact(v0); v1 = gelu_exact(v1);
                v2 = gelu_exact(v2); v3 = gelu_exact(v3);
            }
            *(float2*)&C[(size_t)m       * GN + n] = make_float2(v0, v1);
            *(float2*)&C[(size_t)(m + 8) * GN + n] = make_float2(v2, v3);
        }
    }
}

// ---------------------------------------------------------------------------
// Attention: one warp per (b, h). seq_q=1, seq_k=2. Writes packed-A fp16.
// ---------------------------------------------------------------------------
__global__ __launch_bounds__(256) void attn_kernel(
    const float* __restrict__ Q,  const float* __restrict__ K0, const float* __restrict__ K1,
    const float* __restrict__ V0, const float* __restrict__ V1,
    const float* __restrict__ Sconf, const float* __restrict__ qbias,
    __half* __restrict__ AO)
{
    int gw   = (int)((blockIdx.x * blockDim.x + threadIdx.x) >> 5);
    int lane = threadIdx.x & 31;
    int b = gw >> 4;
    int h = gw & 15;
    size_t base = (size_t)b * DMODEL + h * HDIM;

    float q0 = Q[base + lane], q1 = Q[base + lane + 32];
    if (Sconf) {
        float s = 1.f + Sconf[b];
        q0 = fmaf(s, q0, qbias[h * HDIM + lane]);
        q1 = fmaf(s, q1, qbias[h * HDIM + lane + 32]);
    }
    float s0 = q0 * K0[base + lane] + q1 * K0[base + lane + 32];
    float s1 = q0 * K1[base + lane] + q1 * K1[base + lane + 32];
#pragma unroll
    for (int o = 16; o; o >>= 1) {
        s0 += __shfl_xor_sync(0xffffffffu, s0, o);
        s1 += __shfl_xor_sync(0xffffffffu, s1, o);
    }
    s0 *= 0.125f;
    s1 *= 0.125f;
    float mx = fmaxf(s0, s1);
    float e0 = expf(s0 - mx), e1 = expf(s1 - mx);
    float inv = 1.f / (e0 + e1);
    float a0 = e0 * inv, a1 = e1 * inv;
    float o0 = a0 * V0[base + lane]      + a1 * V1[base + lane];
    float o1 = a0 * V0[base + lane + 32] + a1 * V1[base + lane + 32];

    AO[packA_idx_h((uint32_t)b, (uint32_t)(h * HDIM + lane))]      = __float2half_rn(o0);
    AO[packA_idx_h((uint32_t)b, (uint32_t)(h * HDIM + lane + 32))] = __float2half_rn(o1);
}

// ---------------------------------------------------------------------------
// LayerNorm: one warp per row. Writes packed-A fp16.
// ---------------------------------------------------------------------------
__global__ __launch_bounds__(256) void ln_kernel(
    const float* __restrict__ X,
    const float* __restrict__ gamma, const float* __restrict__ beta,
    __half* __restrict__ Y)
{
    int row  = (int)((blockIdx.x * blockDim.x + threadIdx.x) >> 5);
    int lane = threadIdx.x & 31;
    const float* x = X + (size_t)row * DMODEL;
    float v[32];
    float s = 0.f, sq = 0.f;
#pragma unroll
    for (int i = 0; i < 32; ++i) {
        v[i] = x[lane + 32 * i];
        s += v[i];
        sq += v[i] * v[i];
    }
#pragma unroll
    for (int o = 16; o; o >>= 1) {
        s  += __shfl_xor_sync(0xffffffffu, s, o);
        sq += __shfl_xor_sync(0xffffffffu, sq, o);
    }
    float mean = s * (1.f / 1024.f);
    float var  = sq * (1.f / 1024.f) - mean * mean;
    float rr = rsqrtf(var + 1e-5f);
#pragma unroll
    for (int i = 0; i < 32; ++i) {
        int d = lane + 32 * i;
        float y = (v[i] - mean) * rr * gamma[d] + beta[d];
        Y[packA_idx_h((uint32_t)row, (uint32_t)d)] = __float2half_rn(y);
    }
}

// ---------------------------------------------------------------------------
// Launch
// ---------------------------------------------------------------------------
extern "C" void kernel_launch(void* const* d_in, const int* in_sizes, int n_in,
                              void* d_out, int out_size)
{
    const float* Z_T       = (const float*)d_in[0];
    const float* Z_V       = (const float*)d_in[1];
    const float* Z_A       = (const float*)d_in[2];
    const float* S         = (const float*)d_in[3];
    const float* Wqkv_cons = (const float*)d_in[4];
    const float* bqkv_cons = (const float*)d_in[5];
    const float* Wo_cons   = (const float*)d_in[6];
    const float* bo_cons   = (const float*)d_in[7];
    const float* Wqkv_conf = (const float*)d_in[8];
    const float* bqkv_conf = (const float*)d_in[9];
    const float* Wo_conf   = (const float*)d_in[10];
    const float* bo_conf   = (const float*)d_in[11];
    const float* Wp_cons   = (const float*)d_in[12];
    const float* bp_cons   = (const float*)d_in[13];
    const float* Wp_conf   = (const float*)d_in[14];
    const float* bp_conf   = (const float*)d_in[15];
    const float* gamma     = (const float*)d_in[16];
    const float* beta      = (const float*)d_in[17];
    float* out = (float*)d_out;

    void* pp = nullptr; cudaGetSymbolAddress(&pp, g_pool);
    void* wp = nullptr; cudaGetSymbolAddress(&wp, g_wr);
    float*  pool  = (float*)pp;
    __half* wh    = (__half*)wp;
    __half* hbase = (__half*)(pool + 7ull * SLOT_ELEMS);

    auto F = [&](int i) { return pool + (size_t)i * SLOT_ELEMS; };
    auto P = [&](int j) { return hbase + (size_t)j * SLOT_ELEMS; };
    auto W = [&](int i) { return (const uint4*)(wh + (size_t)i * DD); };
    auto P4 = [&](int j) { return (const uint4*)P(j); };

    cudaFuncSetAttribute(gemm_fp16<false>, cudaFuncAttributeMaxDynamicSharedMemorySize, SMEM_GEMM);
    cudaFuncSetAttribute(gemm_fp16<true>,  cudaFuncAttributeMaxDynamicSharedMemorySize, SMEM_GEMM);

    // --- Pack (fp32 -> fp16 fragment-major) ---
    pack_a<<<2048, 256>>>(Z_T, P(0), SLOT_ELEMS);
    pack_a<<<2048, 256>>>(Z_V, P(1), SLOT_ELEMS);
    pack_a<<<2048, 256>>>(Z_A, P(2), SLOT_ELEMS);   // P(1),P(2) contiguous -> merged M=65536
    pack_w<<<512, 256>>>(Wqkv_cons, wh + 0ull * DD, 3 * DD);
    pack_w<<<512, 256>>>(Wo_cons,   wh + 3ull * DD, DD);
    pack_w<<<512, 256>>>(Wqkv_conf, wh + 4ull * DD, 3 * DD);
    pack_w<<<512, 256>>>(Wo_conf,   wh + 7ull * DD, DD);
    pack_w<<<512, 256>>>(Wp_cons,   wh + 8ull * DD, DD);
    pack_w<<<512, 256>>>(Wp_conf,   wh + 9ull * DD, DD);

    dim3 g1(4, 256), g2(4, 512);   // N tiles of 256

    // --- cons branch QKV (K,V merged over both kv inputs) ---
    gemm_fp16<false><<<g1, 256, SMEM_GEMM>>>(P4(0), W(0), bqkv_cons,        F(0));  // Qc
    gemm_fp16<false><<<g2, 256, SMEM_GEMM>>>(P4(1), W(1), bqkv_cons + 1024, F(1));  // K0c|K1c
    gemm_fp16<false><<<g2, 256, SMEM_GEMM>>>(P4(1), W(2), bqkv_cons + 2048, F(3));  // V0c|V1c
    attn_kernel<<<65536, 256>>>(F(0), F(1), F(2), F(3), F(4),
                                (const float*)0, (const float*)0, P(3));            // AOc

    // --- conf branch QKV (Q raw: bias fused in attn with (1+S) scale) ---
    gemm_fp16<false><<<g1, 256, SMEM_GEMM>>>(P4(0), W(4), (const float*)0,  F(0));  // Qf raw
    gemm_fp16<false><<<g2, 256, SMEM_GEMM>>>(P4(1), W(5), bqkv_conf + 1024, F(1));  // K0f|K1f
    gemm_fp16<false><<<g2, 256, SMEM_GEMM>>>(P4(1), W(6), bqkv_conf + 2048, F(3));  // V0f|V1f
    attn_kernel<<<65536, 256>>>(F(0), F(1), F(2), F(3), F(4),
                                S, bqkv_conf, P(4));                                // AOf

    // --- Output projections ---
    gemm_fp16<false><<<g1, 256, SMEM_GEMM>>>(P4(3), W(3), bo_cons, F(5));           // Cc
    gemm_fp16<false><<<g1, 256, SMEM_GEMM>>>(P4(4), W(7), bo_conf, F(6));           // Cf

    // --- LayerNorm ---
    ln_kernel<<<4096, 256>>>(F(5), gamma, beta, P(5));
    ln_kernel<<<4096, 256>>>(F(6), gamma, beta, P(6));

    // --- Final projection + exact GELU into d_out ---
    gemm_fp16<true><<<g1, 256, SMEM_GEMM>>>(P4(5), W(8), bp_cons, out);
    gemm_fp16<true><<<g1, 256, SMEM_GEMM>>>(P4(6), W(9), bp_conf, out + (size_t)BROWS * DMODEL);
}

// round 6
// speedup vs baseline: 1.1399x; 1.1399x over previous
#include <cuda_runtime.h>
#include <cuda_fp16.h>
#include <cstdint>
#include <cstddef>

// ---------------------------------------------------------------------------
// Problem constants
// ---------------------------------------------------------------------------
#define BROWS  32768
#define DMODEL 1024
#define NHEADS 16
#define HDIM   64

// Scratch (__device__ globals = allocation-guard-safe)
#define SLOT_ELEMS 33554432ull                  // B*D elements
__device__ float g_pool[11ull * SLOT_ELEMS];    // fp32 Cc,Cf + fp16 region
#define DD 1048576ull                           // D*D
__device__ float g_wr[5ull * DD + 8192];        // 10*DD halves weights + bias concat

// fp16 region offsets (in halves, from hbase = pool + 2 fp32 slots)
#define H_ZT   0ull
#define H_ZVA  33554432ull     // 32M
#define H_QOUT 100663296ull    // 96M
#define H_KV   167772160ull    // 160M
#define H_AOC  436207616ull    // 416M
#define H_AOF  469762048ull    // 448M
#define H_LNC  503316480ull    // 480M
#define H_LNF  536870912ull    // 512M

// ---------------------------------------------------------------------------
// Helpers
// ---------------------------------------------------------------------------
__device__ __forceinline__ float gelu_exact(float x) {
    return 0.5f * x * (1.0f + erff(x * 0.70710678118654752440f));
}

// Packed-A (fp16) fragment-major index (same as R4).
__device__ __forceinline__ size_t packA_idx_h(uint32_t row, uint32_t col) {
    uint32_t mtile = row >> 7, r = row & 127;
    uint32_t wm = r >> 6, mt = (r >> 4) & 3, b8 = (r >> 3) & 1, g = r & 7;
    uint32_t kb = col >> 5, c5 = col & 31;
    uint32_t ks = c5 >> 4, c4 = c5 & 15;
    uint32_t hi8 = c4 >> 3, rem = c4 & 7, tig = rem >> 1, lo = rem & 1;
    uint32_t reg = hi8 * 2 + b8;
    uint32_t u = ((wm * 2 + ks) * 4 + mt) * 32 + g * 4 + tig;
    return (((size_t)(mtile * 32 + kb)) << 12) + u * 8 + reg * 2 + lo;
}

// ---------------------------------------------------------------------------
// Pack kernels: fp32 -> fp16 (RN) + fragment-major reorder (R4 layouts)
// ---------------------------------------------------------------------------
__global__ void pack_a(const float* __restrict__ src, __half* __restrict__ dst, size_t n) {
    size_t i  = (size_t)blockIdx.x * blockDim.x + threadIdx.x;
    size_t st = (size_t)gridDim.x * blockDim.x;
    for (; i < n; i += st) {
        uint32_t chunk = (uint32_t)(i >> 12), w = (uint32_t)(i & 4095);
        uint32_t u = w >> 3, h = w & 7;
        uint32_t lane = u & 31, mt = (u >> 5) & 3, ks = (u >> 7) & 1, wm = (u >> 8) & 1;
        uint32_t mtile = chunk >> 5, kb = chunk & 31;
        uint32_t g = lane >> 2, tig = lane & 3;
        uint32_t reg = h >> 1, lo = h & 1;
        uint32_t row = mtile * 128 + wm * 64 + mt * 16 + (reg & 1) * 8 + g;
        uint32_t col = kb * 32 + ks * 16 + (reg >> 1) * 8 + tig * 2 + lo;
        dst[i] = __float2half_rn(src[(size_t)row * 1024 + col]);
    }
}
__global__ void pack_w(const float* __restrict__ src, __half* __restrict__ dst, size_t n) {
    size_t i  = (size_t)blockIdx.x * blockDim.x + threadIdx.x;
    size_t st = (size_t)gridDim.x * blockDim.x;
    for (; i < n; i += st) {
        uint32_t chunk = (uint32_t)(i >> 12), w = (uint32_t)(i & 4095);
        uint32_t u = w >> 3, h = w & 7;
        uint32_t lane = u & 31, p = (u >> 5) & 1, ks = (u >> 6) & 1, wn = (u >> 7) & 3;
        uint32_t ntile = chunk >> 5, kb = chunk & 31;
        uint32_t g = lane >> 2, tig = lane & 3;
        uint32_t reg = h >> 1;
        uint32_t nt = p * 2 + (reg >> 1), breg = reg & 1;
        uint32_t nn = ntile * 128 + wn * 32 + nt * 8 + g;
        uint32_t kk = kb * 32 + ks * 16 + breg * 8 + tig * 2 + (h & 1);
        dst[i] = __float2half_rn(src[(size_t)nn * 1024 + kk]);
    }
}

// Build concatenated bias vectors: biasQ[2048] = [bq_cons, 0], biasKV[4096] = [bk_c, bv_c, bk_f, bv_f]
__global__ void build_bias(const float* __restrict__ bqkv_cons, const float* __restrict__ bqkv_conf,
                           float* __restrict__ biasQ, float* __restrict__ biasKV) {
    int i = blockIdx.x * blockDim.x + threadIdx.x;
    if (i < 2048) biasQ[i] = (i < 1024) ? bqkv_cons[i] : 0.f;
    if (i < 4096) biasKV[i] = (i < 2048) ? bqkv_cons[1024 + i] : bqkv_conf[1024 + (i - 2048)];
}

// ---------------------------------------------------------------------------
// fp16 GEMM (fp32 accum): C = A @ W^T + bias. R4-proven mainloop.
// CTA 128x128x32, 8 warps 2(M)x4(N), warp tile 64x32, mma.m16n8k16, 5 stages.
// ---------------------------------------------------------------------------
#define NST 5
#define SMEM_GEMM (NST * 1024 * 16)   // 81920

template <bool GELU, typename OutT>
__global__ __launch_bounds__(256, 2) void gemm_fp16(
    const uint4* __restrict__ Ap, const uint4* __restrict__ Wp,
    const float* __restrict__ bias, OutT* __restrict__ C, int ldC)
{
    extern __shared__ uint4 sm4[];
    uint4* As = sm4;
    uint4* Bs = sm4 + NST * 512;

    const int tid  = threadIdx.x;
    const int ntb  = blockIdx.x;
    const int mtb  = blockIdx.y;
    const int wid  = tid >> 5;
    const int lane = tid & 31;
    const int wm   = wid >> 2;
    const int wn   = wid & 3;
    const int g    = lane >> 2;
    const int tig  = lane & 3;

    const uint4* Abase = Ap + ((size_t)mtb * 32) * 512;
    const uint4* Bbase = Wp + ((size_t)ntb * 32) * 512;

    auto load_stage = [&](int s, int c) {
        const uint4* ga = Abase + (size_t)c * 512 + tid;
        const uint4* gb = Bbase + (size_t)c * 512 + tid;
        uint4* sa = As + s * 512 + tid;
        uint4* sb = Bs + s * 512 + tid;
#pragma unroll
        for (int j = 0; j < 2; ++j) {
            uint32_t da = (uint32_t)__cvta_generic_to_shared(sa + j * 256);
            asm volatile("cp.async.cg.shared.global [%0], [%1], 16;\n" :: "r"(da), "l"(ga + j * 256));
            uint32_t db = (uint32_t)__cvta_generic_to_shared(sb + j * 256);
            asm volatile("cp.async.cg.shared.global [%0], [%1], 16;\n" :: "r"(db), "l"(gb + j * 256));
        }
        asm volatile("cp.async.commit_group;\n");
    };

    float acc[4][4][4];
#pragma unroll
    for (int i = 0; i < 4; ++i)
#pragma unroll
        for (int j = 0; j < 4; ++j)
#pragma unroll
            for (int k = 0; k < 4; ++k) acc[i][j][k] = 0.f;

#pragma unroll
    for (int s = 0; s < NST - 1; ++s) load_stage(s, s);

    for (int c = 0; c < 32; ++c) {
        asm volatile("cp.async.wait_group %0;\n" :: "n"(NST - 2));
        __syncthreads();
        if (c + NST - 1 < 32) load_stage((c + NST - 1) % NST, c + NST - 1);

        const uint4* A4 = As + (c % NST) * 512 + wm * 256 + lane;
        const uint4* B4 = Bs + (c % NST) * 512 + wn * 128 + lane;
#pragma unroll
        for (int ks = 0; ks < 2; ++ks) {
            uint4 av[4], bv[2];
#pragma unroll
            for (int mt = 0; mt < 4; ++mt) av[mt] = A4[ks * 128 + mt * 32];
#pragma unroll
            for (int p = 0; p < 2; ++p)  bv[p] = B4[ks * 64 + p * 32];
#pragma unroll
            for (int mt = 0; mt < 4; ++mt) {
#pragma unroll
                for (int p = 0; p < 2; ++p) {
                    asm volatile(
                        "mma.sync.aligned.m16n8k16.row.col.f32.f16.f16.f32 "
                        "{%0,%1,%2,%3}, {%4,%5,%6,%7}, {%8,%9}, {%0,%1,%2,%3};\n"
                        : "+f"(acc[mt][2*p][0]), "+f"(acc[mt][2*p][1]),
                          "+f"(acc[mt][2*p][2]), "+f"(acc[mt][2*p][3])
                        : "r"(av[mt].x), "r"(av[mt].y), "r"(av[mt].z), "r"(av[mt].w),
                          "r"(bv[p].x), "r"(bv[p].y));
                    asm volatile(
                        "mma.sync.aligned.m16n8k16.row.col.f32.f16.f16.f32 "
                        "{%0,%1,%2,%3}, {%4,%5,%6,%7}, {%8,%9}, {%0,%1,%2,%3};\n"
                        : "+f"(acc[mt][2*p+1][0]), "+f"(acc[mt][2*p+1][1]),
                          "+f"(acc[mt][2*p+1][2]), "+f"(acc[mt][2*p+1][3])
                        : "r"(av[mt].x), "r"(av[mt].y), "r"(av[mt].z), "r"(av[mt].w),
                          "r"(bv[p].z), "r"(bv[p].w));
                }
            }
        }
    }

    // epilogue
#pragma unroll
    for (int mt = 0; mt < 4; ++mt) {
#pragma unroll
        for (int nt = 0; nt < 4; ++nt) {
            int m = mtb * 128 + wm * 64 + mt * 16 + g;
            int n = ntb * 128 + wn * 32 + nt * 8 + tig * 2;
            float bv0 = bias ? bias[n]     : 0.f;
            float bv1 = bias ? bias[n + 1] : 0.f;
            float v0 = acc[mt][nt][0] + bv0;
            float v1 = acc[mt][nt][1] + bv1;
            float v2 = acc[mt][nt][2] + bv0;
            float v3 = acc[mt][nt][3] + bv1;
            if (GELU) {
                v0 = gelu_exact(v0); v1 = gelu_exact(v1);
                v2 = gelu_exact(v2); v3 = gelu_exact(v3);
            }
            if (sizeof(OutT) == 2) {
                __half2* C2 = (__half2*)C;
                C2[((size_t)m       * ldC + n) >> 1] = __floats2half2_rn(v0, v1);
                C2[((size_t)(m + 8) * ldC + n) >> 1] = __floats2half2_rn(v2, v3);
            } else {
                float* Cf = (float*)C;
                *(float2*)&Cf[(size_t)m       * ldC + n] = make_float2(v0, v1);
                *(float2*)&Cf[(size_t)(m + 8) * ldC + n] = make_float2(v2, v3);
            }
        }
    }
}

// ---------------------------------------------------------------------------
// Attention (both branches): warp per (branch, b, h). Reads fp16 merged GEMM
// outputs; writes packed-A fp16. Lane handles dims 2*lane, 2*lane+1 (half2).
// ---------------------------------------------------------------------------
__global__ __launch_bounds__(256) void attn_kernel(
    const __half* __restrict__ Qout,   // [32768, 2048] cols: Qc | Qf(raw)
    const __half* __restrict__ KV,     // [65536, 4096] cols: Kc | Vc | Kf | Vf
    const float* __restrict__ S, const float* __restrict__ bqkv_conf,
    __half* __restrict__ AOc, __half* __restrict__ AOf)
{
    uint32_t gw = (blockIdx.x * blockDim.x + threadIdx.x) >> 5;
    int lane = threadIdx.x & 31;
    uint32_t branch = gw >> 19;
    uint32_t idx = gw & 0x7FFFFu;
    uint32_t b = idx >> 4, h = idx & 15;

    float2 q = __half22float2(*(const __half2*)(Qout + (size_t)b * 2048 + branch * 1024 + h * 64 + 2 * lane));
    if (branch) {
        float s = 1.f + S[b];
        float2 qb = *(const float2*)(bqkv_conf + h * 64 + 2 * lane);
        q.x = fmaf(s, q.x, qb.x);
        q.y = fmaf(s, q.y, qb.y);
    }
    size_t kvb0 = (size_t)b * 4096 + branch * 2048 + h * 64 + 2 * lane;
    size_t kvb1 = (size_t)(32768 + b) * 4096 + branch * 2048 + h * 64 + 2 * lane;
    float2 k0 = __half22float2(*(const __half2*)(KV + kvb0));
    float2 k1 = __half22float2(*(const __half2*)(KV + kvb1));
    float s0 = q.x * k0.x + q.y * k0.y;
    float s1 = q.x * k1.x + q.y * k1.y;
#pragma unroll
    for (int o = 16; o; o >>= 1) {
        s0 += __shfl_xor_sync(0xffffffffu, s0, o);
        s1 += __shfl_xor_sync(0xffffffffu, s1, o);
    }
    s0 *= 0.125f;
    s1 *= 0.125f;
    float mx = fmaxf(s0, s1);
    float e0 = expf(s0 - mx), e1 = expf(s1 - mx);
    float inv = 1.f / (e0 + e1);
    float a0 = e0 * inv, a1 = e1 * inv;
    float2 v0 = __half22float2(*(const __half2*)(KV + kvb0 + 1024));
    float2 v1 = __half22float2(*(const __half2*)(KV + kvb1 + 1024));
    float ox = a0 * v0.x + a1 * v1.x;
    float oy = a0 * v0.y + a1 * v1.y;

    __half* AO = branch ? AOf : AOc;
    size_t pi = packA_idx_h(b, h * 64 + 2 * lane);   // even col -> half2-aligned
    *(__half2*)(AO + pi) = __floats2half2_rn(ox, oy);
}

// ---------------------------------------------------------------------------
// LayerNorm: warp per row; lane handles dims 2*lane + 64*i. Writes packed fp16.
// ---------------------------------------------------------------------------
__global__ __launch_bounds__(256) void ln_kernel(
    const float* __restrict__ X,
    const float* __restrict__ gamma, const float* __restrict__ beta,
    __half* __restrict__ Y)
{
    int row  = (int)((blockIdx.x * blockDim.x + threadIdx.x) >> 5);
    int lane = threadIdx.x & 31;
    const float* x = X + (size_t)row * DMODEL;
    float2 v[16];
    float s = 0.f, sq = 0.f;
#pragma unroll
    for (int i = 0; i < 16; ++i) {
        v[i] = *(const float2*)(x + 2 * lane + 64 * i);
        s += v[i].x + v[i].y;
        sq += v[i].x * v[i].x + v[i].y * v[i].y;
    }
#pragma unroll
    for (int o = 16; o; o >>= 1) {
        s  += __shfl_xor_sync(0xffffffffu, s, o);
        sq += __shfl_xor_sync(0xffffffffu, sq, o);
    }
    float mean = s * (1.f / 1024.f);
    float var  = sq * (1.f / 1024.f) - mean * mean;
    float rr = rsqrtf(var + 1e-5f);
#pragma unroll
    for (int i = 0; i < 16; ++i) {
        int d = 2 * lane + 64 * i;
        float2 gm = *(const float2*)(gamma + d);
        float2 bt = *(const float2*)(beta + d);
        float y0 = (v[i].x - mean) * rr * gm.x + bt.x;
        float y1 = (v[i].y - mean) * rr * gm.y + bt.y;
        *(__half2*)(Y + packA_idx_h((uint32_t)row, (uint32_t)d)) = __floats2half2_rn(y0, y1);
    }
}

// ---------------------------------------------------------------------------
// Launch
// ---------------------------------------------------------------------------
extern "C" void kernel_launch(void* const* d_in, const int* in_sizes, int n_in,
                              void* d_out, int out_size)
{
    const float* Z_T       = (const float*)d_in[0];
    const float* Z_V       = (const float*)d_in[1];
    const float* Z_A       = (const float*)d_in[2];
    const float* S         = (const float*)d_in[3];
    const float* Wqkv_cons = (const float*)d_in[4];
    const float* bqkv_cons = (const float*)d_in[5];
    const float* Wo_cons   = (const float*)d_in[6];
    const float* bo_cons   = (const float*)d_in[7];
    const float* Wqkv_conf = (const float*)d_in[8];
    const float* bqkv_conf = (const float*)d_in[9];
    const float* Wo_conf   = (const float*)d_in[10];
    const float* bo_conf   = (const float*)d_in[11];
    const float* Wp_cons   = (const float*)d_in[12];
    const float* bp_cons   = (const float*)d_in[13];
    const float* Wp_conf   = (const float*)d_in[14];
    const float* bp_conf   = (const float*)d_in[15];
    const float* gamma     = (const float*)d_in[16];
    const float* beta      = (const float*)d_in[17];
    float* out = (float*)d_out;

    void* pp = nullptr; cudaGetSymbolAddress(&pp, g_pool);
    void* wp = nullptr; cudaGetSymbolAddress(&wp, g_wr);
    float*  pool  = (float*)pp;
    __half* wh    = (__half*)wp;
    __half* hbase = (__half*)(pool + 2ull * SLOT_ELEMS);   // after Cc, Cf fp32

    float* Cc = pool;
    float* Cf = pool + SLOT_ELEMS;
    float* biasQ  = (float*)wp + 5ull * DD;        // 2048
    float* biasKV = biasQ + 2048;                  // 4096

    auto H  = [&](unsigned long long off) { return hbase + off; };
    auto H4 = [&](unsigned long long off) { return (const uint4*)(hbase + off); };
    auto W4 = [&](unsigned long long ddOff) { return (const uint4*)(wh + ddOff * DD); };

    cudaFuncSetAttribute(gemm_fp16<false, __half>, cudaFuncAttributeMaxDynamicSharedMemorySize, SMEM_GEMM);
    cudaFuncSetAttribute(gemm_fp16<false, float>,  cudaFuncAttributeMaxDynamicSharedMemorySize, SMEM_GEMM);
    cudaFuncSetAttribute(gemm_fp16<true,  float>,  cudaFuncAttributeMaxDynamicSharedMemorySize, SMEM_GEMM);

    // --- Pack inputs (fp32 -> fp16 fragment-major) ---
    pack_a<<<2048, 256>>>(Z_T, H(H_ZT), SLOT_ELEMS);
    pack_a<<<2048, 256>>>(Z_V, H(H_ZVA), SLOT_ELEMS);
    pack_a<<<2048, 256>>>(Z_A, H(H_ZVA) + SLOT_ELEMS, SLOT_ELEMS);
    // --- Pack weights (concatenated layouts) ---
    pack_w<<<512, 256>>>(Wqkv_cons,            wh + 0ull * DD, DD);       // Wq_c  -> Q cols 0-1023
    pack_w<<<512, 256>>>(Wqkv_conf,            wh + 1ull * DD, DD);       // Wq_f  -> Q cols 1024-2047
    pack_w<<<512, 256>>>(Wqkv_cons + DD,       wh + 2ull * DD, 2 * DD);   // Wk_c,Wv_c -> KV cols 0-2047
    pack_w<<<512, 256>>>(Wqkv_conf + DD,       wh + 4ull * DD, 2 * DD);   // Wk_f,Wv_f -> KV cols 2048-4095
    pack_w<<<512, 256>>>(Wo_cons,              wh + 6ull * DD, DD);
    pack_w<<<512, 256>>>(Wo_conf,              wh + 7ull * DD, DD);
    pack_w<<<512, 256>>>(Wp_cons,              wh + 8ull * DD, DD);
    pack_w<<<512, 256>>>(Wp_conf,              wh + 9ull * DD, DD);
    build_bias<<<16, 256>>>(bqkv_cons, bqkv_conf, biasQ, biasKV);

    // --- Q both branches: [32768, 2048] fp16 ---
    gemm_fp16<false, __half><<<dim3(16, 256), 256, SMEM_GEMM>>>(
        H4(H_ZT), W4(0), biasQ, H(H_QOUT), 2048);
    // --- K & V, both kv inputs, both branches: [65536, 4096] fp16 ---
    gemm_fp16<false, __half><<<dim3(32, 512), 256, SMEM_GEMM>>>(
        H4(H_ZVA), W4(2), biasKV, H(H_KV), 4096);

    // --- Attention, both branches ---
    attn_kernel<<<131072, 256>>>(H(H_QOUT), H(H_KV), S, bqkv_conf, H(H_AOC), H(H_AOF));

    // --- Output projections (fp32 out for LN) ---
    gemm_fp16<false, float><<<dim3(8, 256), 256, SMEM_GEMM>>>(H4(H_AOC), W4(6), bo_cons, Cc, 1024);
    gemm_fp16<false, float><<<dim3(8, 256), 256, SMEM_GEMM>>>(H4(H_AOF), W4(7), bo_conf, Cf, 1024);

    // --- LayerNorm -> packed fp16 ---
    ln_kernel<<<4096, 256>>>(Cc, gamma, beta, H(H_LNC));
    ln_kernel<<<4096, 256>>>(Cf, gamma, beta, H(H_LNF));

    // --- Final projection + exact GELU into d_out ---
    gemm_fp16<true, float><<<dim3(8, 256), 256, SMEM_GEMM>>>(H4(H_LNC), W4(8), bp_cons, out, 1024);
    gemm_fp16<true, float><<<dim3(8, 256), 256, SMEM_GEMM>>>(H4(H_LNF), W4(9), bp_conf,
                                                             out + (size_t)BROWS * DMODEL, 1024);
}

// round 8
// speedup vs baseline: 1.2961x; 1.1370x over previous
#include <cuda_runtime.h>
#include <cuda_fp16.h>
#include <cstdint>
#include <cstddef>

// ---------------------------------------------------------------------------
// Problem constants
// ---------------------------------------------------------------------------
#define BROWS  32768
#define DMODEL 1024
#define NHEADS 16
#define HDIM   64

// Scratch (__device__ globals = allocation-guard-safe)
#define SLOT_ELEMS 33554432ull                  // B*D elements
__device__ float g_pool[11ull * SLOT_ELEMS];    // all-fp16 working region (704Mi halves)
#define DD 1048576ull                           // D*D
__device__ float g_wr[5ull * DD + 10240];       // 10*DD halves weights + 4 bias vecs

// fp16 region offsets (halves, from hbase = (half*)g_pool)
#define OFF_ZT   0ull
#define OFF_ZVA  33554432ull     // 32Mi
#define OFF_QOUT 100663296ull    // 96Mi
#define OFF_KV   167772160ull    // 160Mi  (65536 x 4096)
#define OFF_AOC  436207616ull    // 416Mi
#define OFF_AOF  469762048ull    // 448Mi (contiguous after AOC)
#define OFF_C    503316480ull    // 480Mi (Wo out, both branches, 64Mi)
#define OFF_LN   570425344ull    // 544Mi (LN out packed, both branches, 64Mi)

// ---------------------------------------------------------------------------
// Helpers
// ---------------------------------------------------------------------------
__device__ __forceinline__ float gelu_exact(float x) {
    return 0.5f * x * (1.0f + erff(x * 0.70710678118654752440f));
}

// Packed-A (fp16) fragment-major index (layout identical to R4/R6).
__device__ __forceinline__ size_t packA_idx_h(uint32_t row, uint32_t col) {
    uint32_t mtile = row >> 7, r = row & 127;
    uint32_t wm = r >> 6, mt = (r >> 4) & 3, b8 = (r >> 3) & 1, g = r & 7;
    uint32_t kb = col >> 5, c5 = col & 31;
    uint32_t ks = c5 >> 4, c4 = c5 & 15;
    uint32_t hi8 = c4 >> 3, rem = c4 & 7, tig = rem >> 1, lo = rem & 1;
    uint32_t reg = hi8 * 2 + b8;
    uint32_t u = ((wm * 2 + ks) * 4 + mt) * 32 + g * 4 + tig;
    return (((size_t)(mtile * 32 + kb)) << 12) + u * 8 + reg * 2 + lo;
}

// ---------------------------------------------------------------------------
// Pack kernels: thread per 16B dst unit (uint4 write, 4x float2 read)
// ---------------------------------------------------------------------------
__global__ void pack_a(const float* __restrict__ src, __half* __restrict__ dst, size_t nunits) {
    size_t j  = (size_t)blockIdx.x * blockDim.x + threadIdx.x;
    size_t st = (size_t)gridDim.x * blockDim.x;
    for (; j < nunits; j += st) {
        uint32_t chunk = (uint32_t)(j >> 9), w = (uint32_t)(j & 511);
        uint32_t lane = w & 31, mt = (w >> 5) & 3, ks = (w >> 7) & 1, wm = (w >> 8) & 1;
        uint32_t mtile = chunk >> 5, kb = chunk & 31;
        uint32_t g = lane >> 2, tig = lane & 3;
        uint32_t r0 = mtile * 128 + wm * 64 + mt * 16 + g;
        uint32_t c0 = kb * 32 + ks * 16 + tig * 2;
        float2 a = *(const float2*)(src + (size_t)r0 * 1024 + c0);
        float2 b = *(const float2*)(src + (size_t)(r0 + 8) * 1024 + c0);
        float2 c = *(const float2*)(src + (size_t)r0 * 1024 + c0 + 8);
        float2 d = *(const float2*)(src + (size_t)(r0 + 8) * 1024 + c0 + 8);
        __half2 h0 = __floats2half2_rn(a.x, a.y);
        __half2 h1 = __floats2half2_rn(b.x, b.y);
        __half2 h2 = __floats2half2_rn(c.x, c.y);
        __half2 h3 = __floats2half2_rn(d.x, d.y);
        uint4 o;
        o.x = *(uint32_t*)&h0; o.y = *(uint32_t*)&h1;
        o.z = *(uint32_t*)&h2; o.w = *(uint32_t*)&h3;
        ((uint4*)dst)[j] = o;
    }
}
__global__ void pack_w(const float* __restrict__ src, __half* __restrict__ dst, size_t nunits) {
    size_t j  = (size_t)blockIdx.x * blockDim.x + threadIdx.x;
    size_t st = (size_t)gridDim.x * blockDim.x;
    for (; j < nunits; j += st) {
        uint32_t chunk = (uint32_t)(j >> 9), w = (uint32_t)(j & 511);
        uint32_t lane = w & 31, p = (w >> 5) & 1, ks = (w >> 6) & 1, wn = (w >> 7) & 3;
        uint32_t ntile = chunk >> 5, kb = chunk & 31;
        uint32_t g = lane >> 2, tig = lane & 3;
        uint32_t n0 = ntile * 128 + wn * 32 + p * 16 + g;
        uint32_t k0 = kb * 32 + ks * 16 + tig * 2;
        float2 a = *(const float2*)(src + (size_t)n0 * 1024 + k0);
        float2 b = *(const float2*)(src + (size_t)n0 * 1024 + k0 + 8);
        float2 c = *(const float2*)(src + (size_t)(n0 + 8) * 1024 + k0);
        float2 d = *(const float2*)(src + (size_t)(n0 + 8) * 1024 + k0 + 8);
        __half2 h0 = __floats2half2_rn(a.x, a.y);
        __half2 h1 = __floats2half2_rn(b.x, b.y);
        __half2 h2 = __floats2half2_rn(c.x, c.y);
        __half2 h3 = __floats2half2_rn(d.x, d.y);
        uint4 o;
        o.x = *(uint32_t*)&h0; o.y = *(uint32_t*)&h1;
        o.z = *(uint32_t*)&h2; o.w = *(uint32_t*)&h3;
        ((uint4*)dst)[j] = o;
    }
}

// Concatenated bias vectors
__global__ void build_bias(const float* __restrict__ bqkv_cons, const float* __restrict__ bqkv_conf,
                           const float* __restrict__ bo_cons, const float* __restrict__ bo_conf,
                           const float* __restrict__ bp_cons, const float* __restrict__ bp_conf,
                           float* __restrict__ biasQ, float* __restrict__ biasKV,
                           float* __restrict__ biasO, float* __restrict__ biasP) {
    int i = blockIdx.x * blockDim.x + threadIdx.x;
    if (i < 2048) {
        biasQ[i] = (i < 1024) ? bqkv_cons[i] : 0.f;
        biasO[i] = (i < 1024) ? bo_cons[i] : bo_conf[i - 1024];
        biasP[i] = (i < 1024) ? bp_cons[i] : bp_conf[i - 1024];
    }
    if (i < 4096) biasKV[i] = (i < 2048) ? bqkv_cons[1024 + i] : bqkv_conf[1024 + (i - 2048)];
}

// ---------------------------------------------------------------------------
// fp16 GEMM (fp32 accum): C = A @ W(sel)^T + bias(sel).
// CTA 128x128, BK=64, 8 warps 2(M)x4(N), warp tile 64x32, mma.m16n8k16, 3 stages.
// Weight/bias selected per M-half (mtb>>8) for merged branch-pair launches.
// ---------------------------------------------------------------------------
#define NST 3
#define SMEM_GEMM (NST * 2048 * 16)   // 98304

template <bool GELU, typename OutT>
__global__ __launch_bounds__(256, 2) void gemm_fp16(
    const uint4* __restrict__ Ap, const uint4* __restrict__ Wp,
    const float* __restrict__ bias, OutT* __restrict__ C, int ldC,
    int wsel_u4, int bias_stride)
{
    extern __shared__ uint4 sm4[];
    uint4* As = sm4;                  // NST * 1024
    uint4* Bs = sm4 + NST * 1024;     // NST * 1024

    const int tid  = threadIdx.x;
    const int ntb  = blockIdx.x;
    const int mtb  = blockIdx.y;
    const int bsel = mtb >> 8;
    const int wid  = tid >> 5;
    const int lane = tid & 31;
    const int wm   = wid >> 2;
    const int wn   = wid & 3;
    const int g    = lane >> 2;
    const int tig  = lane & 3;

    const uint4* Abase = Ap + (size_t)mtb * 16384;
    const uint4* Bbase = Wp + (size_t)bsel * wsel_u4 + (size_t)ntb * 16384;
    const float* biasb = bias + (size_t)bsel * bias_stride;

    auto load_stage = [&](int s, int c) {
        const uint4* ga = Abase + (size_t)c * 1024 + tid;
        const uint4* gb = Bbase + (size_t)c * 1024 + tid;
        uint4* sa = As + s * 1024 + tid;
        uint4* sb = Bs + s * 1024 + tid;
#pragma unroll
        for (int j = 0; j < 4; ++j) {
            uint32_t da = (uint32_t)__cvta_generic_to_shared(sa + j * 256);
            asm volatile("cp.async.cg.shared.global [%0], [%1], 16;\n" :: "r"(da), "l"(ga + j * 256));
            uint32_t db = (uint32_t)__cvta_generic_to_shared(sb + j * 256);
            asm volatile("cp.async.cg.shared.global [%0], [%1], 16;\n" :: "r"(db), "l"(gb + j * 256));
        }
        asm volatile("cp.async.commit_group;\n");
    };

    float acc[4][4][4];
#pragma unroll
    for (int i = 0; i < 4; ++i)
#pragma unroll
        for (int j = 0; j < 4; ++j)
#pragma unroll
            for (int k = 0; k < 4; ++k) acc[i][j][k] = 0.f;

#pragma unroll
    for (int s = 0; s < NST - 1; ++s) load_stage(s, s);

    int st = 0, ld = NST - 1;
    for (int c = 0; c < 16; ++c) {
        asm volatile("cp.async.wait_group %0;\n" :: "n"(NST - 2));
        __syncthreads();
        if (c + NST - 1 < 16) {
            load_stage(ld, c + NST - 1);
            if (++ld == NST) ld = 0;
        }
        const uint4* Abuf = As + st * 1024;
        const uint4* Bbuf = Bs + st * 1024;
#pragma unroll
        for (int ks = 0; ks < 4; ++ks) {
            const int kh  = (ks >> 1) * 512;   // kb-half offset within 64-col chunk
            const int ks2 = ks & 1;
            const uint4* A4 = Abuf + kh + wm * 256 + ks2 * 128 + lane;
            const uint4* B4 = Bbuf + kh + wn * 128 + ks2 * 64 + lane;
            uint4 av[4], bv[2];
#pragma unroll
            for (int mt = 0; mt < 4; ++mt) av[mt] = A4[mt * 32];
#pragma unroll
            for (int p = 0; p < 2; ++p)  bv[p] = B4[p * 32];
#pragma unroll
            for (int mt = 0; mt < 4; ++mt) {
#pragma unroll
                for (int p = 0; p < 2; ++p) {
                    asm volatile(
                        "mma.sync.aligned.m16n8k16.row.col.f32.f16.f16.f32 "
                        "{%0,%1,%2,%3}, {%4,%5,%6,%7}, {%8,%9}, {%0,%1,%2,%3};\n"
                        : "+f"(acc[mt][2*p][0]), "+f"(acc[mt][2*p][1]),
                          "+f"(acc[mt][2*p][2]), "+f"(acc[mt][2*p][3])
                        : "r"(av[mt].x), "r"(av[mt].y), "r"(av[mt].z), "r"(av[mt].w),
                          "r"(bv[p].x), "r"(bv[p].y));
                    asm volatile(
                        "mma.sync.aligned.m16n8k16.row.col.f32.f16.f16.f32 "
                        "{%0,%1,%2,%3}, {%4,%5,%6,%7}, {%8,%9}, {%0,%1,%2,%3};\n"
                        : "+f"(acc[mt][2*p+1][0]), "+f"(acc[mt][2*p+1][1]),
                          "+f"(acc[mt][2*p+1][2]), "+f"(acc[mt][2*p+1][3])
                        : "r"(av[mt].x), "r"(av[mt].y), "r"(av[mt].z), "r"(av[mt].w),
                          "r"(bv[p].z), "r"(bv[p].w));
                }
            }
        }
        if (++st == NST) st = 0;
    }

    // epilogue
#pragma unroll
    for (int mt = 0; mt < 4; ++mt) {
#pragma unroll
        for (int nt = 0; nt < 4; ++nt) {
            int m = mtb * 128 + wm * 64 + mt * 16 + g;
            int n = ntb * 128 + wn * 32 + nt * 8 + tig * 2;
            float bv0 = biasb[n];
            float bv1 = biasb[n + 1];
            float v0 = acc[mt][nt][0] + bv0;
            float v1 = acc[mt][nt][1] + bv1;
            float v2 = acc[mt][nt][2] + bv0;
            float v3 = acc[mt][nt][3] + bv1;
            if (GELU) {
                v0 = gelu_exact(v0); v1 = gelu_exact(v1);
                v2 = gelu_exact(v2); v3 = gelu_exact(v3);
            }
            if (sizeof(OutT) == 2) {
                __half2* C2 = (__half2*)C;
                C2[((size_t)m       * ldC + n) >> 1] = __floats2half2_rn(v0, v1);
                C2[((size_t)(m + 8) * ldC + n) >> 1] = __floats2half2_rn(v2, v3);
            } else {
                float* Cf = (float*)C;
                *(float2*)&Cf[(size_t)m       * ldC + n] = make_float2(v0, v1);
                *(float2*)&Cf[(size_t)(m + 8) * ldC + n] = make_float2(v2, v3);
            }
        }
    }
}

// ---------------------------------------------------------------------------
// Attention (both branches): warp per (branch, b, h). half2 I/O.
// ---------------------------------------------------------------------------
__global__ __launch_bounds__(256) void attn_kernel(
    const __half* __restrict__ Qout,   // [32768, 2048] cols: Qc | Qf(raw)
    const __half* __restrict__ KV,     // [65536, 4096] cols: Kc | Vc | Kf | Vf
    const float* __restrict__ S, const float* __restrict__ bqkv_conf,
    __half* __restrict__ AOc, __half* __restrict__ AOf)
{
    uint32_t gw = (blockIdx.x * blockDim.x + threadIdx.x) >> 5;
    int lane = threadIdx.x & 31;
    uint32_t branch = gw >> 19;
    uint32_t idx = gw & 0x7FFFFu;
    uint32_t b = idx >> 4, h = idx & 15;

    float2 q = __half22float2(*(const __half2*)(Qout + (size_t)b * 2048 + branch * 1024 + h * 64 + 2 * lane));
    if (branch) {
        float s = 1.f + S[b];
        float2 qb = *(const float2*)(bqkv_conf + h * 64 + 2 * lane);
        q.x = fmaf(s, q.x, qb.x);
        q.y = fmaf(s, q.y, qb.y);
    }
    size_t kvb0 = (size_t)b * 4096 + branch * 2048 + h * 64 + 2 * lane;
    size_t kvb1 = (size_t)(32768 + b) * 4096 + branch * 2048 + h * 64 + 2 * lane;
    float2 k0 = __half22float2(*(const __half2*)(KV + kvb0));
    float2 k1 = __half22float2(*(const __half2*)(KV + kvb1));
    float s0 = q.x * k0.x + q.y * k0.y;
    float s1 = q.x * k1.x + q.y * k1.y;
#pragma unroll
    for (int o = 16; o; o >>= 1) {
        s0 += __shfl_xor_sync(0xffffffffu, s0, o);
        s1 += __shfl_xor_sync(0xffffffffu, s1, o);
    }
    s0 *= 0.125f;
    s1 *= 0.125f;
    float mx = fmaxf(s0, s1);
    float e0 = expf(s0 - mx), e1 = expf(s1 - mx);
    float inv = 1.f / (e0 + e1);
    float a0 = e0 * inv, a1 = e1 * inv;
    float2 v0 = __half22float2(*(const __half2*)(KV + kvb0 + 1024));
    float2 v1 = __half22float2(*(const __half2*)(KV + kvb1 + 1024));
    float ox = a0 * v0.x + a1 * v1.x;
    float oy = a0 * v0.y + a1 * v1.y;

    __half* AO = branch ? AOf : AOc;
    *(__half2*)(AO + packA_idx_h(b, h * 64 + 2 * lane)) = __floats2half2_rn(ox, oy);
}

// ---------------------------------------------------------------------------
// LayerNorm (both branches): warp per row of 65536; fp16 in, packed fp16 out.
// ---------------------------------------------------------------------------
__global__ __launch_bounds__(256) void ln_kernel(
    const __half* __restrict__ X,
    const float* __restrict__ gamma, const float* __restrict__ beta,
    __half* __restrict__ Y)
{
    uint32_t row = (blockIdx.x * blockDim.x + threadIdx.x) >> 5;
    int lane = threadIdx.x & 31;
    const __half2* x2 = (const __half2*)(X + (size_t)row * 1024);
    float2 v[16];
    float s = 0.f, sq = 0.f;
#pragma unroll
    for (int i = 0; i < 16; ++i) {
        v[i] = __half22float2(x2[lane + 32 * i]);
        s += v[i].x + v[i].y;
        sq += v[i].x * v[i].x + v[i].y * v[i].y;
    }
#pragma unroll
    for (int o = 16; o; o >>= 1) {
        s  += __shfl_xor_sync(0xffffffffu, s, o);
        sq += __shfl_xor_sync(0xffffffffu, sq, o);
    }
    float mean = s * (1.f / 1024.f);
    float var  = sq * (1.f / 1024.f) - mean * mean;
    float rr = rsqrtf(var + 1e-5f);
#pragma unroll
    for (int i = 0; i < 16; ++i) {
        int d = 2 * (lane + 32 * i);
        float2 gm = *(const float2*)(gamma + d);
        float2 bt = *(const float2*)(beta + d);
        float y0 = (v[i].x - mean) * rr * gm.x + bt.x;
        float y1 = (v[i].y - mean) * rr * gm.y + bt.y;
        *(__half2*)(Y + packA_idx_h(row, (uint32_t)d)) = __floats2half2_rn(y0, y1);
    }
}

// ---------------------------------------------------------------------------
// Launch
// ---------------------------------------------------------------------------
extern "C" void kernel_launch(void* const* d_in, const int* in_sizes, int n_in,
                              void* d_out, int out_size)
{
    const float* Z_T       = (const float*)d_in[0];
    const float* Z_V       = (const float*)d_in[1];
    const float* Z_A       = (const float*)d_in[2];
    const float* S         = (const float*)d_in[3];
    const float* Wqkv_cons = (const float*)d_in[4];
    const float* bqkv_cons = (const float*)d_in[5];
    const float* Wo_cons   = (const float*)d_in[6];
    const float* bo_cons   = (const float*)d_in[7];
    const float* Wqkv_conf = (const float*)d_in[8];
    const float* bqkv_conf = (const float*)d_in[9];
    const float* Wo_conf   = (const float*)d_in[10];
    const float* bo_conf   = (const float*)d_in[11];
    const float* Wp_cons   = (const float*)d_in[12];
    const float* bp_cons   = (const float*)d_in[13];
    const float* Wp_conf   = (const float*)d_in[14];
    const float* bp_conf   = (const float*)d_in[15];
    const float* gamma     = (const float*)d_in[16];
    const float* beta      = (const float*)d_in[17];
    float* out = (float*)d_out;

    void* pp = nullptr; cudaGetSymbolAddress(&pp, g_pool);
    void* wp = nullptr; cudaGetSymbolAddress(&wp, g_wr);
    __half* hbase = (__half*)pp;
    __half* wh    = (__half*)wp;
    float*  wrf   = (float*)wp;

    float* biasQ  = wrf + 5ull * DD;       // 2048
    float* biasKV = biasQ + 2048;          // 4096
    float* biasO  = biasKV + 4096;         // 2048
    float* biasP  = biasO + 2048;          // 2048

    auto H  = [&](unsigned long long off) { return hbase + off; };
    auto H4 = [&](unsigned long long off) { return (const uint4*)(hbase + off); };
    auto W4 = [&](unsigned long long dd) { return (const uint4*)(wh + dd * DD); };
    const int WSEL = (int)(DD / 8);        // one 1024x1024 weight in uint4

    cudaFuncSetAttribute(gemm_fp16<false, __half>, cudaFuncAttributeMaxDynamicSharedMemorySize, SMEM_GEMM);
    cudaFuncSetAttribute(gemm_fp16<true,  float>,  cudaFuncAttributeMaxDynamicSharedMemorySize, SMEM_GEMM);

    // --- Pack inputs (fp32 -> fp16 fragment-major), thread-per-unit ---
    pack_a<<<2048, 256>>>(Z_T, H(OFF_ZT),  SLOT_ELEMS / 8);
    pack_a<<<2048, 256>>>(Z_V, H(OFF_ZVA), SLOT_ELEMS / 8);
    pack_a<<<2048, 256>>>(Z_A, H(OFF_ZVA) + SLOT_ELEMS, SLOT_ELEMS / 8);
    // --- Pack weights ---
    pack_w<<<1024, 256>>>(Wqkv_cons,      wh + 0ull * DD, DD / 8);       // Wq_c
    pack_w<<<1024, 256>>>(Wqkv_conf,      wh + 1ull * DD, DD / 8);       // Wq_f
    pack_w<<<1024, 256>>>(Wqkv_cons + DD, wh + 2ull * DD, 2 * DD / 8);   // Wk_c, Wv_c
    pack_w<<<1024, 256>>>(Wqkv_conf + DD, wh + 4ull * DD, 2 * DD / 8);   // Wk_f, Wv_f
    pack_w<<<1024, 256>>>(Wo_cons,        wh + 6ull * DD, DD / 8);
    pack_w<<<1024, 256>>>(Wo_conf,        wh + 7ull * DD, DD / 8);
    pack_w<<<1024, 256>>>(Wp_cons,        wh + 8ull * DD, DD / 8);
    pack_w<<<1024, 256>>>(Wp_conf,        wh + 9ull * DD, DD / 8);
    build_bias<<<16, 256>>>(bqkv_cons, bqkv_conf, bo_cons, bo_conf, bp_cons, bp_conf,
                            biasQ, biasKV, biasO, biasP);

    // --- Q both branches: [32768, 2048] fp16 ---
    gemm_fp16<false, __half><<<dim3(16, 256), 256, SMEM_GEMM>>>(
        H4(OFF_ZT), W4(0), biasQ, H(OFF_QOUT), 2048, 0, 0);
    // --- K & V, both kv inputs, both branches: [65536, 4096] fp16 ---
    gemm_fp16<false, __half><<<dim3(32, 512), 256, SMEM_GEMM>>>(
        H4(OFF_ZVA), W4(2), biasKV, H(OFF_KV), 4096, 0, 0);

    // --- Attention, both branches ---
    attn_kernel<<<131072, 256>>>(H(OFF_QOUT), H(OFF_KV), S, bqkv_conf, H(OFF_AOC), H(OFF_AOF));

    // --- Output projection, both branches in one launch (fp16 out) ---
    gemm_fp16<false, __half><<<dim3(8, 512), 256, SMEM_GEMM>>>(
        H4(OFF_AOC), W4(6), biasO, H(OFF_C), 1024, WSEL, 1024);

    // --- LayerNorm, both branches ---
    ln_kernel<<<8192, 256>>>(H(OFF_C), gamma, beta, H(OFF_LN));

    // --- Final projection + exact GELU, both branches, into d_out ---
    gemm_fp16<true, float><<<dim3(8, 512), 256, SMEM_GEMM>>>(
        H4(OFF_LN), W4(8), biasP, out, 1024, WSEL, 1024);
}